// round 9
// baseline (speedup 1.0000x reference)
#include <cuda_runtime.h>
#include <cuda_bf16.h>
#include <cstdint>

// HungarianMatcher cost computation, block-diagonal only.
// Shapes: BS=16, Q=1000, NC=80, T=100, NI=8
// Output: C_diag (BS,Q,T) followed by ioa_diag (BS,Q,NI), f32.
//
// Phase 1: dense 2*focal_class_cost for the block's QPB x NC tile (coalesced,
//          all 128 lanes, 5 independent passes) + per-q pred-box table.
// Phase 2: hot loop is pure FMA + LDS broadcasts + 1 rcp per element.
// regs <= 32 so 16 blocks/SM are resident (100% occupancy ceiling).

#define BSZ 16
#define QN  1000
#define NC  80
#define TN  100
#define NIN 8
#define QPB 8    // q rows per block; 125 blocks cover Q=1000 exactly
#define PQW 12   // floats per q row in spq (padded for float4 access)

__global__ __launch_bounds__(128, 16)
void matcher_kernel(const float* __restrict__ logits,
                    const float* __restrict__ pboxes,
                    const float* __restrict__ tboxes,
                    const float* __restrict__ iboxes,
                    const float* __restrict__ img,
                    const float* __restrict__ img_tgt,
                    const int*   __restrict__ tids,
                    float* __restrict__ outC,
                    float* __restrict__ outIoa)
{
    __shared__ float scc[QPB * NC];    // 2*focal class cost, [q_local][class]
    __shared__ float spq[QPB * PQW];   // per-q: raw box(4), norm box(4), parea

    const int b    = blockIdx.y;
    const int q0   = blockIdx.x * QPB;
    const int lane = threadIdx.x;   // 0..99 -> targets, 100..107 -> ign boxes

    const bool isC   = (lane < TN);
    const bool isIoa = (lane >= TN) && (lane < TN + NIN);

    // ---------------- phase 1a: dense focal table (all lanes) ---------------
    // scc[q][c] = 2*(pos - neg), single log:
    //   e = exp(-x); p = 1/(1+e); -log(p) = log(1+e) = L; -log(1-p) = x + L
    // (factor 2 folded into the 0.5/1.5 constants)
    {
        const float* gl = logits + (size_t)(b * QN + q0) * NC;
        #pragma unroll
        for (int k = 0; k < (QPB * NC) / 128; ++k) {      // exactly 5 passes
            const int idx   = k * 128 + lane;
            const float x   = __ldg(gl + idx);            // fully coalesced
            const float e   = __expf(-x);
            const float s   = 1.f + e;
            const float p   = __frcp_rn(s);
            const float L   = __logf(s);
            const float omp = 1.f - p;
            const float pos2 = 0.5f * omp * omp * L;
            const float neg2 = 1.5f * p * p * (x + L);
            scc[idx] = pos2 - neg2;
        }
    }

    // ---------------- phase 1b: per-q pred box table (lanes 0..QPB-1) -------
    if (lane < QPB) {
        const float* im = img + b * 4;
        const float4 pb = *reinterpret_cast<const float4*>(
                              pboxes + (size_t)(b * QN + q0 + lane) * 4);
        float* row = spq + lane * PQW;
        row[0] = pb.x; row[1] = pb.y; row[2] = pb.z; row[3] = pb.w;
        row[4] = pb.x * __frcp_rn(im[0]);
        row[5] = pb.y * __frcp_rn(im[1]);
        row[6] = pb.z * __frcp_rn(im[2]);
        row[7] = pb.w * __frcp_rn(im[3]);
        row[8] = (pb.z - pb.x) * (pb.w - pb.y);   // parea
    }

    // ---------------- per-lane target / ignore data (registers) -------------
    float tx0 = 0.f, ty0 = 0.f, tx1 = 0.f, ty1 = 0.f;
    float tnx0 = 0.f, tny0 = 0.f, tnx1 = 0.f, tny1 = 0.f;
    float tarea = 0.f;
    int   cls = 0;

    if (isC) {
        const int ti = b * TN + lane;
        const float4 tb = *reinterpret_cast<const float4*>(tboxes + ti * 4);
        tx0 = tb.x; ty0 = tb.y; tx1 = tb.z; ty1 = tb.w;
        const float4 it = *reinterpret_cast<const float4*>(img_tgt + ti * 4);
        tnx0 = tx0 * __frcp_rn(it.x);
        tny0 = ty0 * __frcp_rn(it.y);
        tnx1 = tx1 * __frcp_rn(it.z);
        tny1 = ty1 * __frcp_rn(it.w);
        tarea = (tx1 - tx0) * (ty1 - ty0);
        cls = tids[ti];
    } else if (isIoa) {
        const int ii = b * NIN + (lane - TN);
        const float4 ib = *reinterpret_cast<const float4*>(iboxes + ii * 4);
        tx0 = ib.x; ty0 = ib.y; tx1 = ib.z; ty1 = ib.w;
    }

    __syncthreads();

    // ---------------- phase 2: hot loop (short FMA chain, 1 rcp) ------------
    float* outC_lane   = outC   + (size_t)(b * QN + q0) * TN  + lane;
    float* outIoa_lane = outIoa + (size_t)(b * QN + q0) * NIN + (lane - TN);

    #pragma unroll
    for (int i = 0; i < QPB; ++i) {
        const float* row = spq + i * PQW;

        if (isC) {
            const float4 praw = *reinterpret_cast<const float4*>(row);       // bcast
            const float4 pn   = *reinterpret_cast<const float4*>(row + 4);   // bcast
            const float parea = row[8];                                      // bcast
            const float cc2   = scc[i * NC + cls];
            const float px0 = praw.x, py0 = praw.y, px1 = praw.z, py1 = praw.w;

            // L1 bbox cost on normalized boxes
            const float cb = fabsf(pn.x - tnx0) + fabsf(pn.y - tny0)
                           + fabsf(pn.z - tnx1) + fabsf(pn.w - tny1);

            // GIoU with a single reciprocal:
            // giou = inter/uni + uni/enc - 1 = (inter*enc + uni*uni)/(uni*enc) - 1
            const float ixw = fminf(px1, tx1) - fmaxf(px0, tx0);
            const float iyw = fminf(py1, ty1) - fmaxf(py0, ty0);
            const float inter = fmaxf(ixw, 0.f) * fmaxf(iyw, 0.f);
            const float uni = parea + tarea - inter;
            const float exw = fmaxf(px1, tx1) - fminf(px0, tx0);
            const float eyw = fmaxf(py1, ty1) - fminf(py0, ty0);
            const float enc = fmaxf(exw, 0.f) * fmaxf(eyw, 0.f);
            const float r   = __frcp_rn(uni * enc);
            // g2 = 2*giou
            const float g2  = fmaf(inter * enc + uni * uni, 2.f * r, -2.f);

            // C = 5*cb + cc2 - g2   (cc2 = 2*cost_class)
            outC_lane[i * TN] = fmaf(5.f, cb, cc2 - g2);
        } else if (isIoa) {
            const float4 praw = *reinterpret_cast<const float4*>(row);
            const float parea = row[8];
            const float px0 = praw.x, py0 = praw.y, px1 = praw.z, py1 = praw.w;
            const float ixw = fminf(px1, tx1) - fmaxf(px0, tx0);
            const float iyw = fminf(py1, ty1) - fmaxf(py0, ty0);
            const float inter = fmaxf(ixw, 0.f) * fmaxf(iyw, 0.f);
            outIoa_lane[i * NIN] = inter * __frcp_rn(parea);
        }
    }
}

extern "C" void kernel_launch(void* const* d_in, const int* in_sizes, int n_in,
                              void* d_out, int out_size)
{
    const float* logits  = (const float*)d_in[0];
    const float* pboxes  = (const float*)d_in[1];
    const float* tboxes  = (const float*)d_in[2];
    const float* iboxes  = (const float*)d_in[3];
    const float* img     = (const float*)d_in[4];
    const float* img_tgt = (const float*)d_in[5];
    const int*   tids    = (const int*)d_in[6];

    float* outC   = (float*)d_out;
    float* outIoa = (float*)d_out + (size_t)BSZ * QN * TN;

    dim3 grid(QN / QPB, BSZ);   // 125 x 16 = 2000 blocks
    matcher_kernel<<<grid, 128>>>(logits, pboxes, tboxes, iboxes,
                                  img, img_tgt, tids, outC, outIoa);
}

// round 10
// speedup vs baseline: 1.0278x; 1.0278x over previous
#include <cuda_runtime.h>
#include <cuda_bf16.h>
#include <cstdint>

// HungarianMatcher cost computation, block-diagonal only.
// Shapes: BS=16, Q=1000, NC=80, T=100, NI=8
// Output: C_diag (BS,Q,T) followed by ioa_diag (BS,Q,NI), f32.
//
// Phase 1: dense 2*focal_class_cost for the block's QPB x NC tile (coalesced,
//          all 128 lanes, 5 independent passes) + per-q pred-box table.
// Phase 2: hot loop, minimized ALU-pipe work:
//   - enclosure widths via min+max identity: exw = pw + tw - ixw (no FMNMX)
//   - enclosure clamps dropped (widths provably >= 0 for valid boxes)
//   - L1 operands pre-scaled by 5 on both sides (kills final 5*cb multiply)

#define BSZ 16
#define QN  1000
#define NC  80
#define TN  100
#define NIN 8
#define QPB 8    // q rows per block; 125 blocks cover Q=1000 exactly
#define PQW 12   // floats per q row in spq (48B: keeps row+0 / row+8 16B-aligned)

__global__ __launch_bounds__(128, 15)
void matcher_kernel(const float* __restrict__ logits,
                    const float* __restrict__ pboxes,
                    const float* __restrict__ tboxes,
                    const float* __restrict__ iboxes,
                    const float* __restrict__ img,
                    const float* __restrict__ img_tgt,
                    const int*   __restrict__ tids,
                    float* __restrict__ outC,
                    float* __restrict__ outIoa)
{
    __shared__ float scc[QPB * NC];    // 2*focal class cost, [q_local][class]
    __shared__ float spq[QPB * PQW];   // per-q: raw box(4), 5*norm box(4),
                                       //        parea, pw, ph, pad

    const int b    = blockIdx.y;
    const int q0   = blockIdx.x * QPB;
    const int lane = threadIdx.x;   // 0..99 -> targets, 100..107 -> ign boxes

    const bool isC   = (lane < TN);
    const bool isIoa = (lane >= TN) && (lane < TN + NIN);

    // ---------------- phase 1a: dense focal table (all lanes) ---------------
    // scc[q][c] = 2*(pos - neg), single log:
    //   e = exp(-x); p = 1/(1+e); -log(p) = log(1+e) = L; -log(1-p) = x + L
    {
        const float* gl = logits + (size_t)(b * QN + q0) * NC;
        #pragma unroll
        for (int k = 0; k < (QPB * NC) / 128; ++k) {      // exactly 5 passes
            const int idx   = k * 128 + lane;
            const float x   = __ldg(gl + idx);            // fully coalesced
            const float e   = __expf(-x);
            const float s   = 1.f + e;
            const float p   = __frcp_rn(s);
            const float L   = __logf(s);
            const float omp = 1.f - p;
            const float pos2 = 0.5f * omp * omp * L;
            const float neg2 = 1.5f * p * p * (x + L);
            scc[idx] = pos2 - neg2;
        }
    }

    // ---------------- phase 1b: per-q pred box table (lanes 0..QPB-1) -------
    if (lane < QPB) {
        const float* im = img + b * 4;
        const float4 pb = *reinterpret_cast<const float4*>(
                              pboxes + (size_t)(b * QN + q0 + lane) * 4);
        float* row = spq + lane * PQW;
        row[0] = pb.x; row[1] = pb.y; row[2] = pb.z; row[3] = pb.w;
        row[4] = 5.f * pb.x * __frcp_rn(im[0]);   // 5 * normalized box
        row[5] = 5.f * pb.y * __frcp_rn(im[1]);
        row[6] = 5.f * pb.z * __frcp_rn(im[2]);
        row[7] = 5.f * pb.w * __frcp_rn(im[3]);
        row[8]  = (pb.z - pb.x) * (pb.w - pb.y);  // parea
        row[9]  = pb.z - pb.x;                    // pw
        row[10] = pb.w - pb.y;                    // ph
    }

    // ---------------- per-lane target / ignore data (registers) -------------
    float tx0 = 0.f, ty0 = 0.f, tx1 = 0.f, ty1 = 0.f;
    float tn0 = 0.f, tn1 = 0.f, tn2 = 0.f, tn3 = 0.f;   // 5 * normalized tgt
    float tw = 0.f, th = 0.f;
    int   cls = 0;

    if (isC) {
        const int ti = b * TN + lane;
        const float4 tb = *reinterpret_cast<const float4*>(tboxes + ti * 4);
        tx0 = tb.x; ty0 = tb.y; tx1 = tb.z; ty1 = tb.w;
        const float4 it = *reinterpret_cast<const float4*>(img_tgt + ti * 4);
        tn0 = 5.f * tx0 * __frcp_rn(it.x);
        tn1 = 5.f * ty0 * __frcp_rn(it.y);
        tn2 = 5.f * tx1 * __frcp_rn(it.z);
        tn3 = 5.f * ty1 * __frcp_rn(it.w);
        tw = tx1 - tx0;
        th = ty1 - ty0;
        cls = tids[ti];
    } else if (isIoa) {
        const int ii = b * NIN + (lane - TN);
        const float4 ib = *reinterpret_cast<const float4*>(iboxes + ii * 4);
        tx0 = ib.x; ty0 = ib.y; tx1 = ib.z; ty1 = ib.w;
    }

    __syncthreads();

    // ---------------- phase 2: hot loop -------------------------------------
    float* outC_lane   = outC   + (size_t)(b * QN + q0) * TN  + lane;
    float* outIoa_lane = outIoa + (size_t)(b * QN + q0) * NIN + (lane - TN);

    #pragma unroll
    for (int i = 0; i < QPB; ++i) {
        const float* row = spq + i * PQW;

        if (isC) {
            const float4 praw = *reinterpret_cast<const float4*>(row);       // bcast
            const float4 pn   = *reinterpret_cast<const float4*>(row + 4);   // bcast
            const float4 pex  = *reinterpret_cast<const float4*>(row + 8);   // bcast
            const float px0 = praw.x, py0 = praw.y, px1 = praw.z, py1 = praw.w;
            const float parea = pex.x, pw = pex.y, ph = pex.z;
            const float cc2 = scc[i * NC + cls];

            // 5 * L1 bbox cost (operands pre-scaled by 5)
            const float cb5 = fabsf(pn.x - tn0) + fabsf(pn.y - tn1)
                            + fabsf(pn.z - tn2) + fabsf(pn.w - tn3);

            // intersection widths (only 4 FMNMX + 2 clamps)
            const float ixw = fminf(px1, tx1) - fmaxf(px0, tx0);
            const float iyw = fminf(py1, ty1) - fmaxf(py0, ty0);
            const float inter = fmaxf(ixw, 0.f) * fmaxf(iyw, 0.f);

            // enclosure via min+max identity (no FMNMX, no clamps needed)
            const float exw = (pw + tw) - ixw;
            const float eyw = (ph + th) - iyw;
            const float enc = exw * eyw;

            // uni = parea + tarea - inter, tarea folded as tw*th FFMA
            const float uni = fmaf(tw, th, parea - inter);

            // g2 = 2*giou = (inter*enc + uni*uni) * 2/(uni*enc) - 2
            const float r   = __frcp_rn(uni * enc);
            const float g2  = fmaf(fmaf(uni, uni, inter * enc), 2.f * r, -2.f);

            // C = 5*cb + 2*cclass - 2*giou
            outC_lane[i * TN] = (cb5 + cc2) - g2;
        } else if (isIoa) {
            const float4 praw = *reinterpret_cast<const float4*>(row);
            const float parea = row[8];
            const float px0 = praw.x, py0 = praw.y, px1 = praw.z, py1 = praw.w;
            const float ixw = fminf(px1, tx1) - fmaxf(px0, tx0);
            const float iyw = fminf(py1, ty1) - fmaxf(py0, ty0);
            const float inter = fmaxf(ixw, 0.f) * fmaxf(iyw, 0.f);
            outIoa_lane[i * NIN] = inter * __frcp_rn(parea);
        }
    }
}

extern "C" void kernel_launch(void* const* d_in, const int* in_sizes, int n_in,
                              void* d_out, int out_size)
{
    const float* logits  = (const float*)d_in[0];
    const float* pboxes  = (const float*)d_in[1];
    const float* tboxes  = (const float*)d_in[2];
    const float* iboxes  = (const float*)d_in[3];
    const float* img     = (const float*)d_in[4];
    const float* img_tgt = (const float*)d_in[5];
    const int*   tids    = (const int*)d_in[6];

    float* outC   = (float*)d_out;
    float* outIoa = (float*)d_out + (size_t)BSZ * QN * TN;

    dim3 grid(QN / QPB, BSZ);   // 125 x 16 = 2000 blocks
    matcher_kernel<<<grid, 128>>>(logits, pboxes, tboxes, iboxes,
                                  img, img_tgt, tids, outC, outIoa);
}

// round 11
// speedup vs baseline: 1.1866x; 1.1545x over previous
#include <cuda_runtime.h>
#include <cuda_bf16.h>
#include <cstdint>

// HungarianMatcher cost computation, block-diagonal only.
// Shapes: BS=16, Q=1000, NC=80, T=100, NI=8
// Output: C_diag (BS,Q,T) followed by ioa_diag (BS,Q,NI), f32.
//
// Phase 1: dense 2*focal_class_cost for the block's QPB x NC tile (coalesced,
//          all 128 lanes, 5 independent passes) + per-q pred-box table.
// Phase 2: hot loop, minimal ALU work (min+max identity for enclosure) and
//          single-MUFU reciprocals (rcp.approx) everywhere — rcp.rn costs
//          ~7 instrs (Newton + fixup), approx costs 1 and tolerance is 1e-3.

#define BSZ 16
#define QN  1000
#define NC  80
#define TN  100
#define NIN 8
#define QPB 8    // q rows per block; 125 blocks cover Q=1000 exactly
#define PQW 12   // floats per q row in spq (48B: keeps row+0 / row+8 16B-aligned)

// single-MUFU approximate reciprocal (~1 ulp; tolerance is 1e-3)
__device__ __forceinline__ float frcp(float x) {
    float y;
    asm("rcp.approx.ftz.f32 %0, %1;" : "=f"(y) : "f"(x));
    return y;
}

__global__ __launch_bounds__(128, 15)
void matcher_kernel(const float* __restrict__ logits,
                    const float* __restrict__ pboxes,
                    const float* __restrict__ tboxes,
                    const float* __restrict__ iboxes,
                    const float* __restrict__ img,
                    const float* __restrict__ img_tgt,
                    const int*   __restrict__ tids,
                    float* __restrict__ outC,
                    float* __restrict__ outIoa)
{
    __shared__ float scc[QPB * NC];    // 2*focal class cost, [q_local][class]
    __shared__ float spq[QPB * PQW];   // per-q: raw box(4), 5*norm box(4),
                                       //        parea, pw, ph, pad

    const int b    = blockIdx.y;
    const int q0   = blockIdx.x * QPB;
    const int lane = threadIdx.x;   // 0..99 -> targets, 100..107 -> ign boxes

    const bool isC   = (lane < TN);
    const bool isIoa = (lane >= TN) && (lane < TN + NIN);

    // ---------------- phase 1a: dense focal table (all lanes) ---------------
    // scc[q][c] = 2*(pos - neg), single log:
    //   e = exp(-x); p = 1/(1+e); -log(p) = log(1+e) = L; -log(1-p) = x + L
    {
        const float* gl = logits + (size_t)(b * QN + q0) * NC;
        #pragma unroll
        for (int k = 0; k < (QPB * NC) / 128; ++k) {      // exactly 5 passes
            const int idx   = k * 128 + lane;
            const float x   = __ldg(gl + idx);            // fully coalesced
            const float e   = __expf(-x);
            const float s   = 1.f + e;
            const float p   = frcp(s);
            const float L   = __logf(s);
            const float omp = 1.f - p;
            const float pos2 = 0.5f * omp * omp * L;
            const float neg2 = 1.5f * p * p * (x + L);
            scc[idx] = pos2 - neg2;
        }
    }

    // ---------------- phase 1b: per-q pred box table (lanes 0..QPB-1) -------
    if (lane < QPB) {
        const float* im = img + b * 4;
        const float4 pb = *reinterpret_cast<const float4*>(
                              pboxes + (size_t)(b * QN + q0 + lane) * 4);
        float* row = spq + lane * PQW;
        row[0] = pb.x; row[1] = pb.y; row[2] = pb.z; row[3] = pb.w;
        row[4] = 5.f * pb.x * frcp(im[0]);   // 5 * normalized box
        row[5] = 5.f * pb.y * frcp(im[1]);
        row[6] = 5.f * pb.z * frcp(im[2]);
        row[7] = 5.f * pb.w * frcp(im[3]);
        row[8]  = (pb.z - pb.x) * (pb.w - pb.y);  // parea
        row[9]  = pb.z - pb.x;                    // pw
        row[10] = pb.w - pb.y;                    // ph
    }

    // ---------------- per-lane target / ignore data (registers) -------------
    float tx0 = 0.f, ty0 = 0.f, tx1 = 0.f, ty1 = 0.f;
    float tn0 = 0.f, tn1 = 0.f, tn2 = 0.f, tn3 = 0.f;   // 5 * normalized tgt
    float tw = 0.f, th = 0.f;
    int   cls = 0;

    if (isC) {
        const int ti = b * TN + lane;
        const float4 tb = *reinterpret_cast<const float4*>(tboxes + ti * 4);
        tx0 = tb.x; ty0 = tb.y; tx1 = tb.z; ty1 = tb.w;
        const float4 it = *reinterpret_cast<const float4*>(img_tgt + ti * 4);
        tn0 = 5.f * tx0 * frcp(it.x);
        tn1 = 5.f * ty0 * frcp(it.y);
        tn2 = 5.f * tx1 * frcp(it.z);
        tn3 = 5.f * ty1 * frcp(it.w);
        tw = tx1 - tx0;
        th = ty1 - ty0;
        cls = tids[ti];
    } else if (isIoa) {
        const int ii = b * NIN + (lane - TN);
        const float4 ib = *reinterpret_cast<const float4*>(iboxes + ii * 4);
        tx0 = ib.x; ty0 = ib.y; tx1 = ib.z; ty1 = ib.w;
    }

    __syncthreads();

    // ---------------- phase 2: hot loop -------------------------------------
    float* outC_lane   = outC   + (size_t)(b * QN + q0) * TN  + lane;
    float* outIoa_lane = outIoa + (size_t)(b * QN + q0) * NIN + (lane - TN);

    #pragma unroll
    for (int i = 0; i < QPB; ++i) {
        const float* row = spq + i * PQW;

        if (isC) {
            const float4 praw = *reinterpret_cast<const float4*>(row);       // bcast
            const float4 pn   = *reinterpret_cast<const float4*>(row + 4);   // bcast
            const float4 pex  = *reinterpret_cast<const float4*>(row + 8);   // bcast
            const float px0 = praw.x, py0 = praw.y, px1 = praw.z, py1 = praw.w;
            const float parea = pex.x, pw = pex.y, ph = pex.z;
            const float cc2 = scc[i * NC + cls];

            // 5 * L1 bbox cost (operands pre-scaled by 5)
            const float cb5 = fabsf(pn.x - tn0) + fabsf(pn.y - tn1)
                            + fabsf(pn.z - tn2) + fabsf(pn.w - tn3);

            // intersection widths (4 FMNMX + 2 clamps)
            const float ixw = fminf(px1, tx1) - fmaxf(px0, tx0);
            const float iyw = fminf(py1, ty1) - fmaxf(py0, ty0);
            const float inter = fmaxf(ixw, 0.f) * fmaxf(iyw, 0.f);

            // enclosure via min+max identity (no FMNMX, no clamps needed)
            const float exw = (pw + tw) - ixw;
            const float eyw = (ph + th) - iyw;
            const float enc = exw * eyw;

            // uni = parea + tarea - inter, tarea folded as tw*th FFMA
            const float uni = fmaf(tw, th, parea - inter);

            // g2 = 2*giou = (inter*enc + uni*uni) * 2/(uni*enc) - 2
            const float r   = frcp(uni * enc);
            const float g2  = fmaf(fmaf(uni, uni, inter * enc), 2.f * r, -2.f);

            // C = 5*cb + 2*cclass - 2*giou
            outC_lane[i * TN] = (cb5 + cc2) - g2;
        } else if (isIoa) {
            const float4 praw = *reinterpret_cast<const float4*>(row);
            const float parea = row[8];
            const float px0 = praw.x, py0 = praw.y, px1 = praw.z, py1 = praw.w;
            const float ixw = fminf(px1, tx1) - fmaxf(px0, tx0);
            const float iyw = fminf(py1, ty1) - fmaxf(py0, ty0);
            const float inter = fmaxf(ixw, 0.f) * fmaxf(iyw, 0.f);
            outIoa_lane[i * NIN] = inter * frcp(parea);
        }
    }
}

extern "C" void kernel_launch(void* const* d_in, const int* in_sizes, int n_in,
                              void* d_out, int out_size)
{
    const float* logits  = (const float*)d_in[0];
    const float* pboxes  = (const float*)d_in[1];
    const float* tboxes  = (const float*)d_in[2];
    const float* iboxes  = (const float*)d_in[3];
    const float* img     = (const float*)d_in[4];
    const float* img_tgt = (const float*)d_in[5];
    const int*   tids    = (const int*)d_in[6];

    float* outC   = (float*)d_out;
    float* outIoa = (float*)d_out + (size_t)BSZ * QN * TN;

    dim3 grid(QN / QPB, BSZ);   // 125 x 16 = 2000 blocks
    matcher_kernel<<<grid, 128>>>(logits, pboxes, tboxes, iboxes,
                                  img, img_tgt, tids, outC, outIoa);
}

// round 12
// speedup vs baseline: 1.2077x; 1.0178x over previous
#include <cuda_runtime.h>
#include <cuda_bf16.h>
#include <cstdint>

// HungarianMatcher cost computation, block-diagonal only.
// Shapes: BS=16, Q=1000, NC=80, T=100, NI=8
// Output: C_diag (BS,Q,T) followed by ioa_diag (BS,Q,NI), f32.
//
// Phase 1: dense 2*focal_class_cost for the block's QPB x NC tile (coalesced,
//          all 128 lanes, 5 passes) into smem; raw pred boxes into smem.
// Phase 2: hot loop with only 2 LDS per element (raw box bcast + focal gather);
//          normalized-box L1 terms and pred area/width/height recomputed via
//          FFMA from per-lane uniform registers (cheaper than LDS on MIO).

#define BSZ 16
#define QN  1000
#define NC  80
#define TN  100
#define NIN 8
#define QPB 8    // q rows per block; 125 blocks cover Q=1000 exactly

// single-MUFU approximate reciprocal (~1 ulp; tolerance is 1e-3)
__device__ __forceinline__ float frcp(float x) {
    float y;
    asm("rcp.approx.ftz.f32 %0, %1;" : "=f"(y) : "f"(x));
    return y;
}

__global__ __launch_bounds__(128, 15)
void matcher_kernel(const float* __restrict__ logits,
                    const float* __restrict__ pboxes,
                    const float* __restrict__ tboxes,
                    const float* __restrict__ iboxes,
                    const float* __restrict__ img,
                    const float* __restrict__ img_tgt,
                    const int*   __restrict__ tids,
                    float* __restrict__ outC,
                    float* __restrict__ outIoa)
{
    __shared__ float  scc[QPB * NC];   // 2*focal class cost, [q_local][class]
    __shared__ float4 spq[QPB];        // raw pred boxes

    const int b    = blockIdx.y;
    const int q0   = blockIdx.x * QPB;
    const int lane = threadIdx.x;   // 0..99 -> targets, 100..107 -> ign boxes

    const bool isC   = (lane < TN);
    const bool isIoa = (lane >= TN) && (lane < TN + NIN);

    // ---------------- phase 1a: dense focal table (all lanes) ---------------
    // scc[q][c] = 2*(pos - neg), single log:
    //   e = exp(-x); p = 1/(1+e); -log(p) = log(1+e) = L; -log(1-p) = x + L
    {
        const float* gl = logits + (size_t)(b * QN + q0) * NC;
        #pragma unroll
        for (int k = 0; k < (QPB * NC) / 128; ++k) {      // exactly 5 passes
            const int idx   = k * 128 + lane;
            const float x   = __ldg(gl + idx);            // fully coalesced
            const float e   = __expf(-x);
            const float s   = 1.f + e;
            const float p   = frcp(s);
            const float L   = __logf(s);
            const float omp = 1.f - p;
            const float pos2 = 0.5f * omp * omp * L;
            const float neg2 = 1.5f * p * p * (x + L);
            scc[idx] = pos2 - neg2;
        }
    }

    // ---------------- phase 1b: raw pred boxes to smem (lanes 0..QPB-1) -----
    if (lane < QPB) {
        spq[lane] = *reinterpret_cast<const float4*>(
                        pboxes + (size_t)(b * QN + q0 + lane) * 4);
    }

    // ---------------- per-lane uniform + target / ignore data ---------------
    // i0..i3 = 5 / img (uniform across C lanes)
    const float* im = img + b * 4;
    const float i0 = 5.f * frcp(im[0]);
    const float i1 = 5.f * frcp(im[1]);
    const float i2 = 5.f * frcp(im[2]);
    const float i3 = 5.f * frcp(im[3]);

    float tx0 = 0.f, ty0 = 0.f, tx1 = 0.f, ty1 = 0.f;
    float tn0 = 0.f, tn1 = 0.f, tn2 = 0.f, tn3 = 0.f;   // 5 * normalized tgt
    float tw = 0.f, th = 0.f;
    int   cls = 0;

    if (isC) {
        const int ti = b * TN + lane;
        const float4 tb = *reinterpret_cast<const float4*>(tboxes + ti * 4);
        tx0 = tb.x; ty0 = tb.y; tx1 = tb.z; ty1 = tb.w;
        const float4 it = *reinterpret_cast<const float4*>(img_tgt + ti * 4);
        tn0 = 5.f * tx0 * frcp(it.x);
        tn1 = 5.f * ty0 * frcp(it.y);
        tn2 = 5.f * tx1 * frcp(it.z);
        tn3 = 5.f * ty1 * frcp(it.w);
        tw = tx1 - tx0;
        th = ty1 - ty0;
        cls = tids[ti];
    } else if (isIoa) {
        const int ii = b * NIN + (lane - TN);
        const float4 ib = *reinterpret_cast<const float4*>(iboxes + ii * 4);
        tx0 = ib.x; ty0 = ib.y; tx1 = ib.z; ty1 = ib.w;
    }

    __syncthreads();

    // ---------------- phase 2: hot loop (2 LDS + FFMA chain per element) ----
    float* outC_lane   = outC   + (size_t)(b * QN + q0) * TN  + lane;
    float* outIoa_lane = outIoa + (size_t)(b * QN + q0) * NIN + (lane - TN);

    #pragma unroll
    for (int i = 0; i < QPB; ++i) {
        const float4 pb = spq[i];                         // LDS.128 broadcast
        const float px0 = pb.x, py0 = pb.y, px1 = pb.z, py1 = pb.w;
        const float pw = px1 - px0;
        const float ph = py1 - py0;

        if (isC) {
            const float cc2 = scc[i * NC + cls];          // class-indexed LDS

            // 5 * L1 bbox cost: |px*ik - tnk| via FFMA, then abs-modifier adds
            const float d0 = fmaf(px0, i0, -tn0);
            const float d1 = fmaf(py0, i1, -tn1);
            const float d2 = fmaf(px1, i2, -tn2);
            const float d3 = fmaf(py1, i3, -tn3);
            const float cb5 = (fabsf(d0) + fabsf(d1)) + (fabsf(d2) + fabsf(d3));

            // intersection widths (4 FMNMX + 2 clamps)
            const float ixw = fminf(px1, tx1) - fmaxf(px0, tx0);
            const float iyw = fminf(py1, ty1) - fmaxf(py0, ty0);
            const float inter = fmaxf(ixw, 0.f) * fmaxf(iyw, 0.f);

            // enclosure via min+max identity (no FMNMX, no clamps needed)
            const float exw = (pw + tw) - ixw;
            const float eyw = (ph + th) - iyw;
            const float enc = exw * eyw;

            // uni = parea + tarea - inter (both areas as FFMA)
            const float uni = fmaf(tw, th, fmaf(pw, ph, -inter));

            // g2 = 2*giou = (inter*enc + uni*uni) * 2/(uni*enc) - 2
            const float r   = frcp(uni * enc);
            const float g2  = fmaf(fmaf(uni, uni, inter * enc), 2.f * r, -2.f);

            // C = 5*cb + 2*cclass - 2*giou
            outC_lane[i * TN] = (cb5 + cc2) - g2;
        } else if (isIoa) {
            const float ixw = fminf(px1, tx1) - fmaxf(px0, tx0);
            const float iyw = fminf(py1, ty1) - fmaxf(py0, ty0);
            const float inter = fmaxf(ixw, 0.f) * fmaxf(iyw, 0.f);
            outIoa_lane[i * NIN] = inter * frcp(pw * ph);
        }
    }
}

extern "C" void kernel_launch(void* const* d_in, const int* in_sizes, int n_in,
                              void* d_out, int out_size)
{
    const float* logits  = (const float*)d_in[0];
    const float* pboxes  = (const float*)d_in[1];
    const float* tboxes  = (const float*)d_in[2];
    const float* iboxes  = (const float*)d_in[3];
    const float* img     = (const float*)d_in[4];
    const float* img_tgt = (const float*)d_in[5];
    const int*   tids    = (const int*)d_in[6];

    float* outC   = (float*)d_out;
    float* outIoa = (float*)d_out + (size_t)BSZ * QN * TN;

    dim3 grid(QN / QPB, BSZ);   // 125 x 16 = 2000 blocks
    matcher_kernel<<<grid, 128>>>(logits, pboxes, tboxes, iboxes,
                                  img, img_tgt, tids, outC, outIoa);
}

// round 13
// speedup vs baseline: 1.2113x; 1.0030x over previous
#include <cuda_runtime.h>
#include <cuda_bf16.h>
#include <cstdint>

// HungarianMatcher cost computation, block-diagonal only.
// Shapes: BS=16, Q=1000, NC=80, T=100, NI=8
// Output: C_diag (BS,Q,T) followed by ioa_diag (BS,Q,NI), f32.
//
// Phase 1: dense (2*focal_class_cost + 2) for the block's QPB x NC tile
//          (coalesced, all lanes, 5 passes) into smem; raw pred boxes to smem;
//          ioa lanes (100..107) compute their outputs here, straight from
//          gmem, so phase 2 has NO divergent second path in warp 3.
// Phase 2: C-only hot loop: 2 LDS + short FFMA chain + 1 MUFU rcp + STG.

#define BSZ 16
#define QN  1000
#define NC  80
#define TN  100
#define NIN 8
#define QPB 8    // q rows per block; 125 blocks cover Q=1000 exactly

// single-MUFU approximate reciprocal (~1 ulp; tolerance is 1e-3)
__device__ __forceinline__ float frcp(float x) {
    float y;
    asm("rcp.approx.ftz.f32 %0, %1;" : "=f"(y) : "f"(x));
    return y;
}

__global__ __launch_bounds__(128, 15)
void matcher_kernel(const float* __restrict__ logits,
                    const float* __restrict__ pboxes,
                    const float* __restrict__ tboxes,
                    const float* __restrict__ iboxes,
                    const float* __restrict__ img,
                    const float* __restrict__ img_tgt,
                    const int*   __restrict__ tids,
                    float* __restrict__ outC,
                    float* __restrict__ outIoa)
{
    __shared__ float  scc[QPB * NC];   // 2*focal cost + 2, [q_local][class]
    __shared__ float4 spq[QPB];        // raw pred boxes

    const int b    = blockIdx.y;
    const int q0   = blockIdx.x * QPB;
    const int lane = threadIdx.x;   // 0..99 -> targets, 100..107 -> ign boxes

    const bool isC   = (lane < TN);
    const bool isIoa = (lane >= TN) && (lane < TN + NIN);

    const float* pbox_base = pboxes + (size_t)(b * QN + q0) * 4;

    // ---------------- phase 1a: dense focal table (all lanes) ---------------
    // scc[q][c] = 2*(pos - neg) + 2, single log:
    //   e = exp(-x); p = 1/(1+e); -log(p) = log(1+e) = L; -log(1-p) = x + L
    // (the +2 pre-folds the "-(-2)" constant of the giou epilogue)
    {
        const float* gl = logits + (size_t)(b * QN + q0) * NC;
        #pragma unroll
        for (int k = 0; k < (QPB * NC) / 128; ++k) {      // exactly 5 passes
            const int idx   = k * 128 + lane;
            const float x   = __ldg(gl + idx);            // fully coalesced
            const float e   = __expf(-x);
            const float s   = 1.f + e;
            const float p   = frcp(s);
            const float L   = __logf(s);
            const float omp = 1.f - p;
            const float pos2 = 0.5f * omp * omp * L;
            const float neg2 = 1.5f * p * p * (x + L);
            scc[idx] = (pos2 - neg2) + 2.f;
        }
    }

    // ---------------- phase 1b: raw pred boxes to smem (lanes 0..QPB-1) -----
    if (lane < QPB) {
        spq[lane] = *reinterpret_cast<const float4*>(pbox_base + lane * 4);
    }

    // ---------------- ioa lanes: full output, straight from gmem ------------
    // Runs concurrently with other warps' phase-1a; removes the divergent
    // second path from warp 3 in phase 2.
    if (isIoa) {
        const int ii = b * NIN + (lane - TN);
        const float4 ib = *reinterpret_cast<const float4*>(iboxes + ii * 4);
        float* oI = outIoa + (size_t)(b * QN + q0) * NIN + (lane - TN);
        #pragma unroll
        for (int i = 0; i < QPB; ++i) {
            const float4 pb = *reinterpret_cast<const float4*>(pbox_base + i * 4);
            const float ixw = fminf(pb.z, ib.z) - fmaxf(pb.x, ib.x);
            const float iyw = fminf(pb.w, ib.w) - fmaxf(pb.y, ib.y);
            const float inter = fmaxf(ixw, 0.f) * fmaxf(iyw, 0.f);
            const float parea = (pb.z - pb.x) * (pb.w - pb.y);
            oI[i * NIN] = inter * frcp(parea);
        }
    }

    // ---------------- per-lane uniform + target data ------------------------
    const float* im = img + b * 4;
    const float i0 = 5.f * frcp(im[0]);
    const float i1 = 5.f * frcp(im[1]);
    const float i2 = 5.f * frcp(im[2]);
    const float i3 = 5.f * frcp(im[3]);

    float tx0 = 0.f, ty0 = 0.f, tx1 = 0.f, ty1 = 0.f;
    float tn0 = 0.f, tn1 = 0.f, tn2 = 0.f, tn3 = 0.f;   // 5 * normalized tgt
    float tw = 0.f, th = 0.f;
    int   cls = 0;

    if (isC) {
        const int ti = b * TN + lane;
        const float4 tb = *reinterpret_cast<const float4*>(tboxes + ti * 4);
        tx0 = tb.x; ty0 = tb.y; tx1 = tb.z; ty1 = tb.w;
        const float4 it = *reinterpret_cast<const float4*>(img_tgt + ti * 4);
        tn0 = 5.f * tx0 * frcp(it.x);
        tn1 = 5.f * ty0 * frcp(it.y);
        tn2 = 5.f * tx1 * frcp(it.z);
        tn3 = 5.f * ty1 * frcp(it.w);
        tw = tx1 - tx0;
        th = ty1 - ty0;
        cls = tids[ti];
    }

    __syncthreads();

    // ---------------- phase 2: C-only hot loop ------------------------------
    float* outC_lane = outC + (size_t)(b * QN + q0) * TN + lane;

    if (isC) {
        #pragma unroll
        for (int i = 0; i < QPB; ++i) {
            const float4 pb = spq[i];                     // LDS.128 broadcast
            const float px0 = pb.x, py0 = pb.y, px1 = pb.z, py1 = pb.w;
            const float pw = px1 - px0;
            const float ph = py1 - py0;

            const float cc2 = scc[i * NC + cls];          // class-indexed LDS

            // 5 * L1 bbox cost: |px*ik - tnk| via FFMA, abs-modifier adds
            const float d0 = fmaf(px0, i0, -tn0);
            const float d1 = fmaf(py0, i1, -tn1);
            const float d2 = fmaf(px1, i2, -tn2);
            const float d3 = fmaf(py1, i3, -tn3);
            const float cb5 = (fabsf(d0) + fabsf(d1)) + (fabsf(d2) + fabsf(d3));

            // intersection widths (4 FMNMX + 2 clamps)
            const float ixw = fminf(px1, tx1) - fmaxf(px0, tx0);
            const float iyw = fminf(py1, ty1) - fmaxf(py0, ty0);
            const float inter = fmaxf(ixw, 0.f) * fmaxf(iyw, 0.f);

            // enclosure via min+max identity (no FMNMX, no clamps needed)
            const float exw = (pw + tw) - ixw;
            const float eyw = (ph + th) - iyw;
            const float enc = exw * eyw;

            // uni = parea + tarea - inter (both areas as FFMA)
            const float uni = fmaf(tw, th, fmaf(pw, ph, -inter));

            // C = 5*cb + 2*cclass + 2 - 2*(inter*enc + uni^2)/(uni*enc)
            //   = fmaf(M, -2r, cb5 + cc2')   (the +2 lives inside cc2')
            const float M   = fmaf(uni, uni, inter * enc);
            const float n2r = -2.f * frcp(uni * enc);
            outC_lane[i * TN] = fmaf(M, n2r, cb5 + cc2);
        }
    }
}

extern "C" void kernel_launch(void* const* d_in, const int* in_sizes, int n_in,
                              void* d_out, int out_size)
{
    const float* logits  = (const float*)d_in[0];
    const float* pboxes  = (const float*)d_in[1];
    const float* tboxes  = (const float*)d_in[2];
    const float* iboxes  = (const float*)d_in[3];
    const float* img     = (const float*)d_in[4];
    const float* img_tgt = (const float*)d_in[5];
    const int*   tids    = (const int*)d_in[6];

    float* outC   = (float*)d_out;
    float* outIoa = (float*)d_out + (size_t)BSZ * QN * TN;

    dim3 grid(QN / QPB, BSZ);   // 125 x 16 = 2000 blocks
    matcher_kernel<<<grid, 128>>>(logits, pboxes, tboxes, iboxes,
                                  img, img_tgt, tids, outC, outIoa);
}

// round 14
// speedup vs baseline: 1.2149x; 1.0030x over previous
#include <cuda_runtime.h>
#include <cuda_bf16.h>
#include <cstdint>

// HungarianMatcher cost computation, block-diagonal only.
// Shapes: BS=16, Q=1000, NC=80, T=100, NI=8
// Output: C_diag (BS,Q,T) followed by ioa_diag (BS,Q,NI), f32.
//
// Phase 1: dense (2*focal + 2) table for the block's QPB x NC tile (coalesced,
//          5 passes, refactored: cost2 = r^2*(0.5*e^2*L - 1.5*(x+L)) + 2);
//          raw pred boxes to smem; ioa lanes finish their output here.
// Phase 2: C-only hot loop; the 8 class-gather LDS are hoisted into registers
//          right after the barrier so the per-iteration chain is LDS.128 +
//          FFMA chain + 1 MUFU rcp + STG.

#define BSZ 16
#define QN  1000
#define NC  80
#define TN  100
#define NIN 8
#define QPB 8    // q rows per block; 125 blocks cover Q=1000 exactly

// single-MUFU approximate reciprocal (~1 ulp; tolerance is 1e-3)
__device__ __forceinline__ float frcp(float x) {
    float y;
    asm("rcp.approx.ftz.f32 %0, %1;" : "=f"(y) : "f"(x));
    return y;
}
__device__ __forceinline__ float flg2(float x) {
    float y;
    asm("lg2.approx.ftz.f32 %0, %1;" : "=f"(y) : "f"(x));
    return y;
}

__global__ __launch_bounds__(128, 12)
void matcher_kernel(const float* __restrict__ logits,
                    const float* __restrict__ pboxes,
                    const float* __restrict__ tboxes,
                    const float* __restrict__ iboxes,
                    const float* __restrict__ img,
                    const float* __restrict__ img_tgt,
                    const int*   __restrict__ tids,
                    float* __restrict__ outC,
                    float* __restrict__ outIoa)
{
    __shared__ float  scc[QPB * NC];   // 2*focal cost + 2, [q_local][class]
    __shared__ float4 spq[QPB];        // raw pred boxes

    const int b    = blockIdx.y;
    const int q0   = blockIdx.x * QPB;
    const int lane = threadIdx.x;   // 0..99 -> targets, 100..107 -> ign boxes

    const bool isC   = (lane < TN);
    const bool isIoa = (lane >= TN) && (lane < TN + NIN);

    const float* pbox_base = pboxes + (size_t)(b * QN + q0) * 4;

    // ---------------- phase 1a: dense focal table (all lanes) ---------------
    // p = r = 1/(1+e), 1-p = e*r, L = log(1+e) = lg2(1+e)*ln2
    // cost2 = 2*(pos-neg)+2 = r^2*(0.5*e^2*L - 1.5*(x+L)) + 2
    //       = r^2*(  (e^2*lam)*(0.5*ln2) - 1.5*fma(lam, ln2, x) ) + 2
    {
        const float* gl = logits + (size_t)(b * QN + q0) * NC;
        #pragma unroll
        for (int k = 0; k < (QPB * NC) / 128; ++k) {      // exactly 5 passes
            const int idx   = k * 128 + lane;
            const float x   = __ldg(gl + idx);            // fully coalesced
            const float e   = __expf(-x);                 // mul + ex2
            const float s   = 1.f + e;
            const float r   = frcp(s);
            const float lam = flg2(s);
            const float t   = e * e;
            const float a   = t * lam;                    // e^2 * lg2(s)
            const float u   = fmaf(lam, 0.69314718f, x);  // x + L
            const float v   = -1.5f * u;
            const float inner = fmaf(a, 0.34657359f, v);  // 0.5*ln2*a - 1.5u
            const float r2  = r * r;
            scc[idx] = fmaf(r2, inner, 2.f);
        }
    }

    // ---------------- phase 1b: raw pred boxes to smem (lanes 0..QPB-1) -----
    if (lane < QPB) {
        spq[lane] = *reinterpret_cast<const float4*>(pbox_base + lane * 4);
    }

    // ---------------- ioa lanes: full output, straight from gmem ------------
    if (isIoa) {
        const int ii = b * NIN + (lane - TN);
        const float4 ib = *reinterpret_cast<const float4*>(iboxes + ii * 4);
        float* oI = outIoa + (size_t)(b * QN + q0) * NIN + (lane - TN);
        #pragma unroll
        for (int i = 0; i < QPB; ++i) {
            const float4 pb = *reinterpret_cast<const float4*>(pbox_base + i * 4);
            const float ixw = fminf(pb.z, ib.z) - fmaxf(pb.x, ib.x);
            const float iyw = fminf(pb.w, ib.w) - fmaxf(pb.y, ib.y);
            const float inter = fmaxf(ixw, 0.f) * fmaxf(iyw, 0.f);
            const float parea = (pb.z - pb.x) * (pb.w - pb.y);
            oI[i * NIN] = inter * frcp(parea);
        }
    }

    // ---------------- per-lane uniform + target data ------------------------
    // i0..i3 = 5 / img. image_size_xyxy_tgt carries the same [W,H,W,H] per
    // row as image_size_xyxy, so the target normalization reuses i0..i3.
    const float* im = img + b * 4;
    const float i0 = 5.f * frcp(im[0]);
    const float i1 = 5.f * frcp(im[1]);
    const float i2 = 5.f * frcp(im[2]);
    const float i3 = 5.f * frcp(im[3]);

    float tx0 = 0.f, ty0 = 0.f, tx1 = 0.f, ty1 = 0.f;
    float tn0 = 0.f, tn1 = 0.f, tn2 = 0.f, tn3 = 0.f;   // 5 * normalized tgt
    float tw = 0.f, th = 0.f;
    int   cls = 0;

    if (isC) {
        const int ti = b * TN + lane;
        const float4 tb = *reinterpret_cast<const float4*>(tboxes + ti * 4);
        tx0 = tb.x; ty0 = tb.y; tx1 = tb.z; ty1 = tb.w;
        tn0 = tx0 * i0;
        tn1 = ty0 * i1;
        tn2 = tx1 * i2;
        tn3 = ty1 * i3;
        tw = tx1 - tx0;
        th = ty1 - ty0;
        cls = tids[ti];
    }

    __syncthreads();

    // ---------------- phase 2: C-only hot loop ------------------------------
    float* outC_lane = outC + (size_t)(b * QN + q0) * TN + lane;

    if (isC) {
        // hoist the 8 class gathers: independent LDS, latencies overlap once
        float cc[QPB];
        #pragma unroll
        for (int i = 0; i < QPB; ++i) cc[i] = scc[i * NC + cls];

        #pragma unroll
        for (int i = 0; i < QPB; ++i) {
            const float4 pb = spq[i];                     // LDS.128 broadcast
            const float px0 = pb.x, py0 = pb.y, px1 = pb.z, py1 = pb.w;
            const float pw = px1 - px0;
            const float ph = py1 - py0;

            // 5 * L1 bbox cost: |px*ik - tnk| via FFMA, abs-modifier adds
            const float d0 = fmaf(px0, i0, -tn0);
            const float d1 = fmaf(py0, i1, -tn1);
            const float d2 = fmaf(px1, i2, -tn2);
            const float d3 = fmaf(py1, i3, -tn3);
            const float cb5 = (fabsf(d0) + fabsf(d1)) + (fabsf(d2) + fabsf(d3));

            // intersection widths (4 FMNMX + 2 clamps)
            const float ixw = fminf(px1, tx1) - fmaxf(px0, tx0);
            const float iyw = fminf(py1, ty1) - fmaxf(py0, ty0);
            const float inter = fmaxf(ixw, 0.f) * fmaxf(iyw, 0.f);

            // enclosure via min+max identity (no FMNMX, no clamps)
            const float exw = (pw + tw) - ixw;
            const float eyw = (ph + th) - iyw;
            const float enc = exw * eyw;

            // uni = parea + tarea - inter (both areas as FFMA)
            const float uni = fmaf(tw, th, fmaf(pw, ph, -inter));

            // C = cb5 + cc' - 2*(inter*enc + uni^2)/(uni*enc)
            const float M   = fmaf(uni, uni, inter * enc);
            const float n2r = -2.f * frcp(uni * enc);
            outC_lane[i * TN] = fmaf(M, n2r, cb5 + cc[i]);
        }
    }
}

extern "C" void kernel_launch(void* const* d_in, const int* in_sizes, int n_in,
                              void* d_out, int out_size)
{
    const float* logits  = (const float*)d_in[0];
    const float* pboxes  = (const float*)d_in[1];
    const float* tboxes  = (const float*)d_in[2];
    const float* iboxes  = (const float*)d_in[3];
    const float* img     = (const float*)d_in[4];
    const float* img_tgt = (const float*)d_in[5];
    const int*   tids    = (const int*)d_in[6];

    float* outC   = (float*)d_out;
    float* outIoa = (float*)d_out + (size_t)BSZ * QN * TN;

    dim3 grid(QN / QPB, BSZ);   // 125 x 16 = 2000 blocks
    matcher_kernel<<<grid, 128>>>(logits, pboxes, tboxes, iboxes,
                                  img, img_tgt, tids, outC, outIoa);
}

// round 15
// speedup vs baseline: 1.4034x; 1.1552x over previous
#include <cuda_runtime.h>
#include <cuda_bf16.h>
#include <cstdint>

// HungarianMatcher cost computation, block-diagonal only.
// Shapes: BS=16, Q=1000, NC=80, T=100, NI=8
// Output: C_diag (BS,Q,T) followed by ioa_diag (BS,Q,NI), f32.
//
// Phase 1: dense (2*focal + 2) table for the block's QPB x NC tile (coalesced,
//          5 passes, refactored: cost2 = r^2*(0.5*e^2*L - 1.5*(x+L)) + 2);
//          raw pred boxes to smem; ioa lanes finish their output here.
// Phase 2: C-only hot loop: 2 LDS + short FFMA chain + 1 MUFU rcp + STG.
// Register budget <= 34 (launch_bounds 128,15): R12's occupancy with R13's
// instruction count — the cc[] register hoist is dropped (it cost 8 regs of
// occupancy for latency that wasn't on the critical path).

#define BSZ 16
#define QN  1000
#define NC  80
#define TN  100
#define NIN 8
#define QPB 8    // q rows per block; 125 blocks cover Q=1000 exactly

// single-MUFU approximate reciprocal (~1 ulp; tolerance is 1e-3)
__device__ __forceinline__ float frcp(float x) {
    float y;
    asm("rcp.approx.ftz.f32 %0, %1;" : "=f"(y) : "f"(x));
    return y;
}
__device__ __forceinline__ float flg2(float x) {
    float y;
    asm("lg2.approx.ftz.f32 %0, %1;" : "=f"(y) : "f"(x));
    return y;
}

__global__ __launch_bounds__(128, 15)
void matcher_kernel(const float* __restrict__ logits,
                    const float* __restrict__ pboxes,
                    const float* __restrict__ tboxes,
                    const float* __restrict__ iboxes,
                    const float* __restrict__ img,
                    const float* __restrict__ img_tgt,
                    const int*   __restrict__ tids,
                    float* __restrict__ outC,
                    float* __restrict__ outIoa)
{
    __shared__ float  scc[QPB * NC];   // 2*focal cost + 2, [q_local][class]
    __shared__ float4 spq[QPB];        // raw pred boxes

    const int b    = blockIdx.y;
    const int q0   = blockIdx.x * QPB;
    const int lane = threadIdx.x;   // 0..99 -> targets, 100..107 -> ign boxes

    const bool isC   = (lane < TN);
    const bool isIoa = (lane >= TN) && (lane < TN + NIN);

    const float* pbox_base = pboxes + (size_t)(b * QN + q0) * 4;

    // ---------------- phase 1a: dense focal table (all lanes) ---------------
    // p = r = 1/(1+e), 1-p = e*r, L = log(1+e) = lg2(1+e)*ln2
    // cost2 = 2*(pos-neg)+2 = r^2*(0.5*e^2*L - 1.5*(x+L)) + 2
    {
        const float* gl = logits + (size_t)(b * QN + q0) * NC;
        #pragma unroll
        for (int k = 0; k < (QPB * NC) / 128; ++k) {      // exactly 5 passes
            const int idx   = k * 128 + lane;
            const float x   = __ldg(gl + idx);            // fully coalesced
            const float e   = __expf(-x);                 // mul + ex2
            const float s   = 1.f + e;
            const float r   = frcp(s);
            const float lam = flg2(s);
            const float t   = e * e;
            const float a   = t * lam;                    // e^2 * lg2(s)
            const float u   = fmaf(lam, 0.69314718f, x);  // x + L
            const float v   = -1.5f * u;
            const float inner = fmaf(a, 0.34657359f, v);  // 0.5*ln2*a - 1.5u
            const float r2  = r * r;
            scc[idx] = fmaf(r2, inner, 2.f);
        }
    }

    // ---------------- phase 1b: raw pred boxes to smem (lanes 0..QPB-1) -----
    if (lane < QPB) {
        spq[lane] = *reinterpret_cast<const float4*>(pbox_base + lane * 4);
    }

    // ---------------- ioa lanes: full output, straight from gmem ------------
    if (isIoa) {
        const int ii = b * NIN + (lane - TN);
        const float4 ib = *reinterpret_cast<const float4*>(iboxes + ii * 4);
        float* oI = outIoa + (size_t)(b * QN + q0) * NIN + (lane - TN);
        #pragma unroll
        for (int i = 0; i < QPB; ++i) {
            const float4 pb = *reinterpret_cast<const float4*>(pbox_base + i * 4);
            const float ixw = fminf(pb.z, ib.z) - fmaxf(pb.x, ib.x);
            const float iyw = fminf(pb.w, ib.w) - fmaxf(pb.y, ib.y);
            const float inter = fmaxf(ixw, 0.f) * fmaxf(iyw, 0.f);
            const float parea = (pb.z - pb.x) * (pb.w - pb.y);
            oI[i * NIN] = inter * frcp(parea);
        }
    }

    // ---------------- per-lane uniform + target data ------------------------
    // i0..i3 = 5 / img. image_size_xyxy_tgt carries the same [W,H,W,H] per
    // row as image_size_xyxy, so the target normalization reuses i0..i3.
    const float* im = img + b * 4;
    const float i0 = 5.f * frcp(im[0]);
    const float i1 = 5.f * frcp(im[1]);
    const float i2 = 5.f * frcp(im[2]);
    const float i3 = 5.f * frcp(im[3]);

    float tx0 = 0.f, ty0 = 0.f, tx1 = 0.f, ty1 = 0.f;
    float tn0 = 0.f, tn1 = 0.f, tn2 = 0.f, tn3 = 0.f;   // 5 * normalized tgt
    float tw = 0.f, th = 0.f;
    const float* sccls = scc;   // per-lane gather base (scc + cls)

    if (isC) {
        const int ti = b * TN + lane;
        const float4 tb = *reinterpret_cast<const float4*>(tboxes + ti * 4);
        tx0 = tb.x; ty0 = tb.y; tx1 = tb.z; ty1 = tb.w;
        tn0 = tx0 * i0;
        tn1 = ty0 * i1;
        tn2 = tx1 * i2;
        tn3 = ty1 * i3;
        tw = tx1 - tx0;
        th = ty1 - ty0;
        sccls = scc + tids[ti];
    }

    __syncthreads();

    // ---------------- phase 2: C-only hot loop ------------------------------
    float* outC_lane = outC + (size_t)(b * QN + q0) * TN + lane;

    if (isC) {
        #pragma unroll
        for (int i = 0; i < QPB; ++i) {
            const float4 pb = spq[i];                     // LDS.128 broadcast
            const float cc2 = sccls[i * NC];              // class gather (imm offs)
            const float px0 = pb.x, py0 = pb.y, px1 = pb.z, py1 = pb.w;
            const float pw = px1 - px0;
            const float ph = py1 - py0;

            // 5 * L1 bbox cost: |px*ik - tnk| via FFMA, abs-modifier adds
            const float d0 = fmaf(px0, i0, -tn0);
            const float d1 = fmaf(py0, i1, -tn1);
            const float d2 = fmaf(px1, i2, -tn2);
            const float d3 = fmaf(py1, i3, -tn3);
            const float cb5 = (fabsf(d0) + fabsf(d1)) + (fabsf(d2) + fabsf(d3));

            // intersection widths (4 FMNMX + 2 clamps)
            const float ixw = fminf(px1, tx1) - fmaxf(px0, tx0);
            const float iyw = fminf(py1, ty1) - fmaxf(py0, ty0);
            const float inter = fmaxf(ixw, 0.f) * fmaxf(iyw, 0.f);

            // enclosure via min+max identity (no FMNMX, no clamps)
            const float exw = (pw + tw) - ixw;
            const float eyw = (ph + th) - iyw;
            const float enc = exw * eyw;

            // uni = parea + tarea - inter (both areas as FFMA)
            const float uni = fmaf(tw, th, fmaf(pw, ph, -inter));

            // C = cb5 + cc' - 2*(inter*enc + uni^2)/(uni*enc)
            const float M   = fmaf(uni, uni, inter * enc);
            const float n2r = -2.f * frcp(uni * enc);
            outC_lane[i * TN] = fmaf(M, n2r, cb5 + cc2);
        }
    }
}

extern "C" void kernel_launch(void* const* d_in, const int* in_sizes, int n_in,
                              void* d_out, int out_size)
{
    const float* logits  = (const float*)d_in[0];
    const float* pboxes  = (const float*)d_in[1];
    const float* tboxes  = (const float*)d_in[2];
    const float* iboxes  = (const float*)d_in[3];
    const float* img     = (const float*)d_in[4];
    const float* img_tgt = (const float*)d_in[5];
    const int*   tids    = (const int*)d_in[6];

    float* outC   = (float*)d_out;
    float* outIoa = (float*)d_out + (size_t)BSZ * QN * TN;

    dim3 grid(QN / QPB, BSZ);   // 125 x 16 = 2000 blocks
    matcher_kernel<<<grid, 128>>>(logits, pboxes, tboxes, iboxes,
                                  img, img_tgt, tids, outC, outIoa);
}